// round 2
// baseline (speedup 1.0000x reference)
#include <cuda_runtime.h>
#include <math.h>

// Problem constants
#define BB   16
#define CC   128
#define HW   4096          // 64*64
#define NN   65536         // BB*HW
#define KK   1024
#define Q_ELEMS (BB*CC*HW) // 1048576
#define OUT_IDX_OFF Q_ELEMS
#define OUT_SCAL_OFF (Q_ELEMS + NN)

// Scratch (no allocation allowed)
__device__ float  g_ct[CC * KK];     // transposed codebook [k][code]
__device__ float  g_cc[KK];          // ||c_k||^2 (fp32, sequential rounded, like ref)
__device__ int    g_idx[NN];         // argmin indices
__device__ int    g_counts[KK];      // code usage counts
__device__ double g_partial[NN/64];  // per-block loss partials (1024 blocks)

// ---------------------------------------------------------------------------
// K1: transpose codebook, compute row norms (ref-rounding: fl(c*c) then fl add,
// sequential), zero counts
// ---------------------------------------------------------------------------
__global__ void k_prep(const float* __restrict__ cb) {
    int g = blockIdx.x * blockDim.x + threadIdx.x;
    if (g < CC * KK) {
        int code = g >> 7;       // /128
        int k    = g & 127;
        g_ct[k * KK + code] = cb[g];
    }
    if (g < KK) {
        const float* row = cb + g * CC;
        float s = 0.f;
        for (int i = 0; i < CC; i++)
            s = __fadd_rn(s, __fmul_rn(row[i], row[i]));
        g_cc[g] = s;
        g_counts[g] = 0;
    }
}

// ---------------------------------------------------------------------------
// K2: distance + fused argmin, replicating the reference's fp32 rounding:
//   d2 = fl( fl(S_z - 2*G) + S_c ),  argmin with first-index tie-break.
// Block: 256 threads handles 64 rows x all 1024 codes (8 tiles of 128).
// Dynamic smem: Zs [128][64] (32KB) + Cs [128][128] (64KB) = 96KB.
// ---------------------------------------------------------------------------
__global__ __launch_bounds__(256, 2)
void k_dist(const float* __restrict__ z, float* __restrict__ out_idx_f) {
    extern __shared__ float sm[];
    __shared__ float szrow[64];     // S_z per row (sequential fp32, ref order)
    float* Zs = sm;                 // [k][row]  k*64 + r
    float* Cs = sm + CC * 64;       // [k][code] k*128 + c

    const int tid = threadIdx.x;
    const int n0  = blockIdx.x * 64;
    const int b   = n0 >> 12;       // /4096
    const int hw0 = n0 & 4095;
    const float* zb = z + (size_t)b * CC * HW + hw0;

    // Load Zs: z[b, c, hw0+r] -> Zs[c*64 + r]; coalesced over r.
    {
        int r  = tid & 63;
        int c0 = tid >> 6;          // 0..3
        #pragma unroll
        for (int c = c0; c < CC; c += 4)
            Zs[c * 64 + r] = zb[c * HW + r];
    }
    __syncthreads();

    // S_z per row: STRICTLY sequential over c with rounded mul then rounded
    // add — must match ref's jnp.sum(z*z, axis=1) accumulation.
    if (tid < 64) {
        float acc = 0.f;
        for (int c = 0; c < CC; c++) {
            float v = Zs[c * 64 + tid];
            acc = __fadd_rn(acc, __fmul_rn(v, v));
        }
        szrow[tid] = acc;
    }

    const int cg = tid & 15;        // code group (16)
    const int rg = tid >> 4;        // row group  (16), rows rg*4..rg*4+3

    float best[4];
    int   bidx[4];
    #pragma unroll
    for (int r = 0; r < 4; r++) { best[r] = 3.4e38f; bidx[r] = 0; }

    for (int t = 0; t < 8; t++) {
        const int tb = t * 128;
        __syncthreads();  // prev tile done; also covers szrow/Zs publication
        // Load Cs[k][c] = g_ct[k*1024 + tb + c]; coalesced over c.
        for (int i = tid; i < 128 * 128; i += 256) {
            int k = i >> 7, c = i & 127;
            Cs[i] = g_ct[k * KK + tb + c];
        }
        __syncthreads();

        float accA[4][4], accB[4][4];
        #pragma unroll
        for (int r = 0; r < 4; r++)
            #pragma unroll
            for (int j = 0; j < 4; j++) { accA[r][j] = 0.f; accB[r][j] = 0.f; }

        const float* zp  = Zs + rg * 4;
        const float* cpA = Cs + cg * 4;
        const float* cpB = Cs + 64 + cg * 4;

        #pragma unroll 8
        for (int k = 0; k < 128; k++) {
            float4 a  = *(const float4*)(zp  + k * 64);
            float4 bA = *(const float4*)(cpA + k * 128);
            float4 bB = *(const float4*)(cpB + k * 128);
            float ar[4]  = {a.x, a.y, a.z, a.w};
            float bAv[4] = {bA.x, bA.y, bA.z, bA.w};
            float bBv[4] = {bB.x, bB.y, bB.z, bB.w};
            #pragma unroll
            for (int r = 0; r < 4; r++) {
                #pragma unroll
                for (int j = 0; j < 4; j++) {
                    accA[r][j] = fmaf(ar[r], bAv[j], accA[r][j]);
                    accB[r][j] = fmaf(ar[r], bBv[j], accB[r][j]);
                }
            }
        }

        // Epilogue: d2 = fl( fl(S_z - 2*G) + S_c ); running first-index argmin
        float4 ccA = *(const float4*)(g_cc + tb + cg * 4);
        float4 ccB = *(const float4*)(g_cc + tb + 64 + cg * 4);
        float ccAv[4] = {ccA.x, ccA.y, ccA.z, ccA.w};
        float ccBv[4] = {ccB.x, ccB.y, ccB.z, ccB.w};
        #pragma unroll
        for (int r = 0; r < 4; r++) {
            float sz = szrow[rg * 4 + r];
            #pragma unroll
            for (int j = 0; j < 4; j++) {
                float s = __fadd_rn(__fsub_rn(sz, __fmul_rn(2.0f, accA[r][j])), ccAv[j]);
                int id = tb + cg * 4 + j;
                if (s < best[r] || (s == best[r] && id < bidx[r])) { best[r] = s; bidx[r] = id; }
                s = __fadd_rn(__fsub_rn(sz, __fmul_rn(2.0f, accB[r][j])), ccBv[j]);
                id += 64;
                if (s < best[r] || (s == best[r] && id < bidx[r])) { best[r] = s; bidx[r] = id; }
            }
        }
    }

    // Cross-thread reduction over the 16 code-groups per row (reuse smem)
    __syncthreads();
    float* redv = sm;                       // [64][16]
    int*   redi = (int*)(sm + 64 * 16);     // [64][16]
    #pragma unroll
    for (int r = 0; r < 4; r++) {
        int row = rg * 4 + r;
        redv[row * 16 + cg] = best[r];
        redi[row * 16 + cg] = bidx[r];
    }
    __syncthreads();
    if (tid < 64) {
        float bv = redv[tid * 16];
        int   bi = redi[tid * 16];
        #pragma unroll
        for (int j = 1; j < 16; j++) {
            float v = redv[tid * 16 + j];
            int  ii = redi[tid * 16 + j];
            if (v < bv || (v == bv && ii < bi)) { bv = v; bi = ii; }
        }
        g_idx[n0 + tid] = bi;
        out_idx_f[n0 + tid] = (float)bi;
    }
}

// ---------------------------------------------------------------------------
// K3: gather codebook rows, write quantized (STE-forward replicated),
// accumulate per-block (z-q)^2 partials, code-usage counts.
// ---------------------------------------------------------------------------
__global__ __launch_bounds__(256)
void k_quant(const float* __restrict__ z, const float* __restrict__ cb,
             float* __restrict__ out_q) {
    __shared__ int   idx_s[64];
    __shared__ float qs[64][129];    // padded: conflict-free
    __shared__ double red[256];

    const int tid = threadIdx.x;
    const int n0  = blockIdx.x * 64;
    const int b   = n0 >> 12;
    const int hw0 = n0 & 4095;

    if (tid < 64) {
        int idx = g_idx[n0 + tid];
        idx_s[tid] = idx;
        atomicAdd(&g_counts[idx], 1);
    }
    __syncthreads();

    for (int g = tid; g < 64 * 128; g += 256) {
        int hw = g >> 7, k = g & 127;
        qs[hw][k] = cb[idx_s[hw] * CC + k];
    }
    __syncthreads();

    const float* zb = z     + (size_t)b * CC * HW + hw0;
    float*       ob = out_q + (size_t)b * CC * HW + hw0;
    const int hw = tid & 63;
    const int c0 = tid >> 6;

    double acc = 0.0;
    #pragma unroll 8
    for (int i = 0; i < 32; i++) {
        int c = c0 + i * 4;
        float zv = zb[c * HW + hw];
        float qv = qs[hw][c];
        // replicate ref: quantized = z + (q_raw - z) in fp32
        ob[c * HW + hw] = __fadd_rn(zv, __fsub_rn(qv, zv));
        float d = __fsub_rn(zv, qv);
        acc += (double)d * (double)d;
    }

    red[tid] = acc;
    __syncthreads();
    #pragma unroll
    for (int s = 128; s > 0; s >>= 1) {
        if (tid < s) red[tid] += red[tid + s];
        __syncthreads();
    }
    if (tid == 0) g_partial[blockIdx.x] = red[0];
}

// ---------------------------------------------------------------------------
// K4: finalize — vq_loss and perplexity (deterministic fixed-order reduce)
// ---------------------------------------------------------------------------
__global__ __launch_bounds__(256)
void k_final(float* __restrict__ out) {
    __shared__ double red[256];
    const int tid = threadIdx.x;

    double a = 0.0;
    for (int i = tid; i < NN/64; i += 256) a += g_partial[i];
    red[tid] = a;
    __syncthreads();
    #pragma unroll
    for (int s = 128; s > 0; s >>= 1) {
        if (tid < s) red[tid] += red[tid + s];
        __syncthreads();
    }
    if (tid == 0) {
        double mse = red[0] / (double)Q_ELEMS;
        float m = (float)mse;
        out[OUT_SCAL_OFF + 0] = __fadd_rn(m, 0.25f * m);
    }
    __syncthreads();

    double e = 0.0;
    for (int i = tid; i < KK; i += 256) {
        float p = (float)g_counts[i] / 65536.0f;
        float term = p * logf(p + 1e-10f);   // p=0 -> 0 exactly, like ref
        e += (double)term;
    }
    red[tid] = e;
    __syncthreads();
    #pragma unroll
    for (int s = 128; s > 0; s >>= 1) {
        if (tid < s) red[tid] += red[tid + s];
        __syncthreads();
    }
    if (tid == 0)
        out[OUT_SCAL_OFF + 1] = expf((float)(-red[0]));
}

// ---------------------------------------------------------------------------
extern "C" void kernel_launch(void* const* d_in, const int* in_sizes, int n_in,
                              void* d_out, int out_size) {
    const float* z  = (const float*)d_in[0];  // [16,128,64,64]
    const float* cb = (const float*)d_in[1];  // [1024,128]
    float* out = (float*)d_out;               // [quantized | indices | vq | ppl]

    static bool attr_set = false;
    if (!attr_set) {
        cudaFuncSetAttribute(k_dist, cudaFuncAttributeMaxDynamicSharedMemorySize,
                             96 * 1024);
        attr_set = true;
    }

    k_prep <<<512, 256>>>(cb);
    k_dist <<<NN / 64, 256, 96 * 1024>>>(z, out + OUT_IDX_OFF);
    k_quant<<<NN / 64, 256>>>(z, cb, out);
    k_final<<<1, 256>>>(out);
}

// round 4
// speedup vs baseline: 1.2257x; 1.2257x over previous
#include <cuda_runtime.h>
#include <math.h>

// Problem constants
#define BB   16
#define CC   128
#define HW   4096          // 64*64
#define NN   65536         // BB*HW
#define KK   1024
#define Q_ELEMS (BB*CC*HW) // 1048576
#define OUT_IDX_OFF Q_ELEMS
#define OUT_SCAL_OFF (Q_ELEMS + NN)

// Scratch (no allocation allowed)
__device__ float  g_ct[CC * KK];     // transposed codebook [k][code]
__device__ float  g_cc[KK];          // ||c_k||^2 (fp32, sequential rounded)
__device__ int    g_idx[NN];         // argmin indices
__device__ int    g_counts[KK];      // code usage counts
__device__ double g_partial[NN/64];  // per-block loss partials (1024 blocks)

// Packed fp32x2 FMA (sm_100+): two IEEE-rn fp32 FMAs per instruction.
// Rounding per lane identical to scalar fmaf -> G bits unchanged vs scalar.
#define FFMA2(acc, a, b) \
    asm("fma.rn.f32x2 %0, %1, %2, %0;" : "+l"(acc) : "l"(a), "l"(b))

__device__ __forceinline__ unsigned long long pack2(float lo, float hi) {
    unsigned long long r;
    asm("mov.b64 %0, {%1, %2};" : "=l"(r) : "f"(lo), "f"(hi));
    return r;
}
__device__ __forceinline__ void unpack2(float& lo, float& hi,
                                        unsigned long long v) {
    asm("mov.b64 {%0, %1}, %2;" : "=f"(lo), "=f"(hi) : "l"(v));
}

// ---------------------------------------------------------------------------
// K1: transpose codebook, row norms (ref rounding: fl(c*c) then fl add,
// sequential), zero counts
// ---------------------------------------------------------------------------
__global__ void k_prep(const float* __restrict__ cb) {
    int g = blockIdx.x * blockDim.x + threadIdx.x;
    if (g < CC * KK) {
        int code = g >> 7;       // /128
        int k    = g & 127;
        g_ct[k * KK + code] = cb[g];
    }
    if (g < KK) {
        const float* row = cb + g * CC;
        float s = 0.f;
        for (int i = 0; i < CC; i++)
            s = __fadd_rn(s, __fmul_rn(row[i], row[i]));
        g_cc[g] = s;
        g_counts[g] = 0;
    }
}

// ---------------------------------------------------------------------------
// K2: distance + fused argmin with FFMA2 inner loop.
//   d2 = fl( fl(S_z - 2*G) + S_c ),  argmin with first-index tie-break.
// Block: 256 threads handles 64 rows x all 1024 codes (8 tiles of 128).
// Dynamic smem: Zs [128][64] (32KB) + Cs [128][128] (64KB) = 96KB.
// Thread micro-tile: 4 rows x 8 codes; accumulators packed as f32x2 pairs.
// ---------------------------------------------------------------------------
__global__ __launch_bounds__(256, 2)
void k_dist(const float* __restrict__ z, float* __restrict__ out_idx_f) {
    extern __shared__ float sm[];
    __shared__ float szrow[64];     // S_z per row (sequential fp32, ref order)
    float* Zs = sm;                 // [k][row]  k*64 + r
    float* Cs = sm + CC * 64;       // [k][code] k*128 + c

    const int tid = threadIdx.x;
    const int n0  = blockIdx.x * 64;
    const int b   = n0 >> 12;       // /4096
    const int hw0 = n0 & 4095;
    const float* zb = z + (size_t)b * CC * HW + hw0;

    // Load Zs: z[b, c, hw0+r] -> Zs[c*64 + r]; coalesced over r.
    {
        int r  = tid & 63;
        int c0 = tid >> 6;          // 0..3
        #pragma unroll
        for (int c = c0; c < CC; c += 4)
            Zs[c * 64 + r] = zb[c * HW + r];
    }
    __syncthreads();

    // S_z per row: STRICTLY sequential over c (matches ref jnp.sum(z*z)).
    if (tid < 64) {
        float acc = 0.f;
        for (int c = 0; c < CC; c++) {
            float v = Zs[c * 64 + tid];
            acc = __fadd_rn(acc, __fmul_rn(v, v));
        }
        szrow[tid] = acc;
    }

    const int cg = tid & 15;        // code group (16)
    const int rg = tid >> 4;        // row group  (16), rows rg*4..rg*4+3

    float best[4];
    int   bidx[4];
    #pragma unroll
    for (int r = 0; r < 4; r++) { best[r] = 3.4e38f; bidx[r] = 0; }

    for (int t = 0; t < 8; t++) {
        const int tb = t * 128;
        __syncthreads();  // prev tile done; also covers szrow/Zs publication
        // Load Cs[k][c] = g_ct[k*1024 + tb + c]; coalesced over c.
        for (int i = tid; i < 128 * 128; i += 256) {
            int k = i >> 7, c = i & 127;
            Cs[i] = g_ct[k * KK + tb + c];
        }
        __syncthreads();

        // Packed accumulators: accX2[r][p] holds codes (4p, 4p+1) pairs...
        // layout: [r][0]=(j0,j1), [r][1]=(j2,j3) for the A 4-code group,
        // same for B group.
        unsigned long long accA2[4][2], accB2[4][2];
        #pragma unroll
        for (int r = 0; r < 4; r++) {
            accA2[r][0] = 0ULL; accA2[r][1] = 0ULL;
            accB2[r][0] = 0ULL; accB2[r][1] = 0ULL;
        }

        const float* zp  = Zs + rg * 4;
        const float* cpA = Cs + cg * 4;
        const float* cpB = Cs + 64 + cg * 4;

        #pragma unroll 8
        for (int k = 0; k < 128; k++) {
            float4 a = *(const float4*)(zp + k * 64);
            ulonglong2 bA = *(const ulonglong2*)(cpA + k * 128);
            ulonglong2 bB = *(const ulonglong2*)(cpB + k * 128);
            unsigned long long ad[4];
            ad[0] = pack2(a.x, a.x);
            ad[1] = pack2(a.y, a.y);
            ad[2] = pack2(a.z, a.z);
            ad[3] = pack2(a.w, a.w);
            #pragma unroll
            for (int r = 0; r < 4; r++) {
                FFMA2(accA2[r][0], ad[r], bA.x);
                FFMA2(accA2[r][1], ad[r], bA.y);
                FFMA2(accB2[r][0], ad[r], bB.x);
                FFMA2(accB2[r][1], ad[r], bB.y);
            }
        }

        // Epilogue: d2 = fl( fl(S_z - 2*G) + S_c ); running first-index argmin
        float4 ccA = *(const float4*)(g_cc + tb + cg * 4);
        float4 ccB = *(const float4*)(g_cc + tb + 64 + cg * 4);
        float ccAv[4] = {ccA.x, ccA.y, ccA.z, ccA.w};
        float ccBv[4] = {ccB.x, ccB.y, ccB.z, ccB.w};
        #pragma unroll
        for (int r = 0; r < 4; r++) {
            float sz = szrow[rg * 4 + r];
            float accA[4], accB[4];
            unpack2(accA[0], accA[1], accA2[r][0]);
            unpack2(accA[2], accA[3], accA2[r][1]);
            unpack2(accB[0], accB[1], accB2[r][0]);
            unpack2(accB[2], accB[3], accB2[r][1]);
            #pragma unroll
            for (int j = 0; j < 4; j++) {
                float s = __fadd_rn(__fsub_rn(sz, __fmul_rn(2.0f, accA[j])), ccAv[j]);
                int id = tb + cg * 4 + j;
                if (s < best[r] || (s == best[r] && id < bidx[r])) { best[r] = s; bidx[r] = id; }
                s = __fadd_rn(__fsub_rn(sz, __fmul_rn(2.0f, accB[j])), ccBv[j]);
                id += 64;
                if (s < best[r] || (s == best[r] && id < bidx[r])) { best[r] = s; bidx[r] = id; }
            }
        }
    }

    // Cross-thread reduction over the 16 code-groups per row (reuse smem)
    __syncthreads();
    float* redv = sm;                       // [64][16]
    int*   redi = (int*)(sm + 64 * 16);     // [64][16]
    #pragma unroll
    for (int r = 0; r < 4; r++) {
        int row = rg * 4 + r;
        redv[row * 16 + cg] = best[r];
        redi[row * 16 + cg] = bidx[r];
    }
    __syncthreads();
    if (tid < 64) {
        float bv = redv[tid * 16];
        int   bi = redi[tid * 16];
        #pragma unroll
        for (int j = 1; j < 16; j++) {
            float v = redv[tid * 16 + j];
            int  ii = redi[tid * 16 + j];
            if (v < bv || (v == bv && ii < bi)) { bv = v; bi = ii; }
        }
        g_idx[n0 + tid] = bi;
        out_idx_f[n0 + tid] = (float)bi;
    }
}

// ---------------------------------------------------------------------------
// K3: gather codebook rows, write quantized (STE-forward replicated),
// accumulate per-block (z-q)^2 partials, code-usage counts.
// ---------------------------------------------------------------------------
__global__ __launch_bounds__(256)
void k_quant(const float* __restrict__ z, const float* __restrict__ cb,
             float* __restrict__ out_q) {
    __shared__ int   idx_s[64];
    __shared__ float qs[64][129];    // padded: conflict-free
    __shared__ double red[256];

    const int tid = threadIdx.x;
    const int n0  = blockIdx.x * 64;
    const int b   = n0 >> 12;
    const int hw0 = n0 & 4095;

    if (tid < 64) {
        int idx = g_idx[n0 + tid];
        idx_s[tid] = idx;
        atomicAdd(&g_counts[idx], 1);
    }
    __syncthreads();

    for (int g = tid; g < 64 * 128; g += 256) {
        int hw = g >> 7, k = g & 127;
        qs[hw][k] = cb[idx_s[hw] * CC + k];
    }
    __syncthreads();

    const float* zb = z     + (size_t)b * CC * HW + hw0;
    float*       ob = out_q + (size_t)b * CC * HW + hw0;
    const int hw = tid & 63;
    const int c0 = tid >> 6;

    double acc = 0.0;
    #pragma unroll 8
    for (int i = 0; i < 32; i++) {
        int c = c0 + i * 4;
        float zv = zb[c * HW + hw];
        float qv = qs[hw][c];
        // replicate ref: quantized = z + (q_raw - z) in fp32
        ob[c * HW + hw] = __fadd_rn(zv, __fsub_rn(qv, zv));
        float d = __fsub_rn(zv, qv);
        acc += (double)d * (double)d;
    }

    red[tid] = acc;
    __syncthreads();
    #pragma unroll
    for (int s = 128; s > 0; s >>= 1) {
        if (tid < s) red[tid] += red[tid + s];
        __syncthreads();
    }
    if (tid == 0) g_partial[blockIdx.x] = red[0];
}

// ---------------------------------------------------------------------------
// K4: finalize — vq_loss and perplexity (deterministic fixed-order reduce)
// ---------------------------------------------------------------------------
__global__ __launch_bounds__(256)
void k_final(float* __restrict__ out) {
    __shared__ double red[256];
    const int tid = threadIdx.x;

    double a = 0.0;
    for (int i = tid; i < NN/64; i += 256) a += g_partial[i];
    red[tid] = a;
    __syncthreads();
    #pragma unroll
    for (int s = 128; s > 0; s >>= 1) {
        if (tid < s) red[tid] += red[tid + s];
        __syncthreads();
    }
    if (tid == 0) {
        double mse = red[0] / (double)Q_ELEMS;
        float m = (float)mse;
        out[OUT_SCAL_OFF + 0] = __fadd_rn(m, 0.25f * m);
    }
    __syncthreads();

    double e = 0.0;
    for (int i = tid; i < KK; i += 256) {
        float p = (float)g_counts[i] / 65536.0f;
        float term = p * logf(p + 1e-10f);   // p=0 -> 0 exactly, like ref
        e += (double)term;
    }
    red[tid] = e;
    __syncthreads();
    #pragma unroll
    for (int s = 128; s > 0; s >>= 1) {
        if (tid < s) red[tid] += red[tid + s];
        __syncthreads();
    }
    if (tid == 0)
        out[OUT_SCAL_OFF + 1] = expf((float)(-red[0]));
}

// ---------------------------------------------------------------------------
extern "C" void kernel_launch(void* const* d_in, const int* in_sizes, int n_in,
                              void* d_out, int out_size) {
    const float* z  = (const float*)d_in[0];  // [16,128,64,64]
    const float* cb = (const float*)d_in[1];  // [1024,128]
    float* out = (float*)d_out;               // [quantized | indices | vq | ppl]

    static bool attr_set = false;
    if (!attr_set) {
        cudaFuncSetAttribute(k_dist, cudaFuncAttributeMaxDynamicSharedMemorySize,
                             96 * 1024);
        attr_set = true;
    }

    k_prep <<<512, 256>>>(cb);
    k_dist <<<NN / 64, 256, 96 * 1024>>>(z, out + OUT_IDX_OFF);
    k_quant<<<NN / 64, 256>>>(z, cb, out);
    k_final<<<1, 256>>>(out);
}

// round 9
// speedup vs baseline: 1.2940x; 1.0557x over previous
#include <cuda_runtime.h>
#include <cuda_bf16.h>
#include <math.h>
#include <stdint.h>

// Problem constants
#define BB   16
#define CC   128
#define HW   4096          // 64*64
#define NN   65536         // BB*HW
#define KK   1024
#define Q_ELEMS (BB*CC*HW) // 1048576
#define OUT_IDX_OFF Q_ELEMS
#define OUT_SCAL_OFF (Q_ELEMS + NN)

#define M_CTA  128
#define CAP    32
#define MARGIN 2e-3f       // hard-bound-safe screening margin (see analysis)

// k_screen dynamic smem layout (bytes)
#define ZS_OFF   0         // bf16 zs[128 rows][136 halves]   (34816 B)
#define CBS_OFF  34816     // bf16 cbs[128 codes][136 halves] (34816 B)
#define CCS_OFF  69632     // f32  ccs[1024]                  (4096 B)
#define CAND_OFF 73728     // u16  cand[128][32]              (8192 B)
#define CNT_OFF  81920     // s32  cnt[128]                   (512 B)
#define SM_DYN   82944

// Scratch (no allocation allowed)
__device__ __nv_bfloat16 g_cbh[KK * CC]; // bf16 codebook (row-major)
__device__ float  g_cc[KK];              // ||c_k||^2 (fp32 sequential chain)
__device__ int    g_idx[NN];             // argmin indices
__device__ int    g_counts[KK];          // code usage counts
__device__ double g_partial[NN/64];      // per-block loss partials

// ---------------------------------------------------------------------------
// K1: codebook -> bf16, row norms (ref rounding chain), zero counts
// ---------------------------------------------------------------------------
__global__ void k_prep(const float* __restrict__ cb) {
    int g = blockIdx.x * blockDim.x + threadIdx.x;
    if (g < CC * KK)
        g_cbh[g] = __float2bfloat16(cb[g]);
    if (g < KK) {
        const float* row = cb + g * CC;
        float s = 0.f;
        for (int i = 0; i < CC; i++)
            s = __fadd_rn(s, __fmul_rn(row[i], row[i]));
        g_cc[g] = s;
        g_counts[g] = 0;
    }
}

// ---------------------------------------------------------------------------
// K2: bf16 mma.sync screening + exact fp32 rescoring (fused).
// Grid 512 CTAs x 256 threads (8 warps). CTA: 128 rows vs all 1024 codes.
// Warp w owns rows w*16..w*16+15 (m16n8k16: A row-major, B col-major).
// Screening score s~ = cc - 2*(z_bf16 . c_bf16); exact rescore of candidates
// with the R2 bit-exact chain d2 = fl(fl(S_z - 2G) + S_c).
// ---------------------------------------------------------------------------
__global__ __launch_bounds__(256, 2)
void k_screen(const float* __restrict__ z, const float* __restrict__ cb,
              float* __restrict__ out_idx_f) {
    extern __shared__ char smem[];
    uint32_t* zs32  = (uint32_t*)(smem + ZS_OFF);
    uint32_t* cbs32 = (uint32_t*)(smem + CBS_OFF);
    float*    ccs   = (float*)(smem + CCS_OFF);
    uint16_t* cand  = (uint16_t*)(smem + CAND_OFF);
    int*      cnt   = (int*)(smem + CNT_OFF);

    const int tid  = threadIdx.x;
    const int lane = tid & 31;
    const int wrow = (tid >> 5) * 16;
    const int g    = lane >> 2;
    const int t    = lane & 3;
    const int n0   = blockIdx.x * M_CTA;
    const int b    = n0 >> 12;
    const int hw0  = n0 & 4095;
    const float* zb = z + (size_t)b * CC * HW + hw0;

    if (tid < 128) cnt[tid] = 0;
    for (int i = tid; i < KK; i += 256) ccs[i] = g_cc[i];

    // Stage z as bf16: zs[hw][k], stride 136 halves. Coalesced gmem reads.
    for (int i = tid; i < 128 * 128; i += 256) {
        int k = i >> 7, hw = i & 127;
        ((__nv_bfloat16*)(smem + ZS_OFF))[hw * 136 + k] =
            __float2bfloat16(zb[k * HW + hw]);
    }
    __syncthreads();

    // A fragments (persist whole kernel): 8 k-tiles x 4 regs.
    // m16n8k16 A layout: a0(r=g,k=2t), a1(r=g+8,k=2t), a2(r=g,k=2t+8), a3(r=g+8,k=2t+8)
    uint32_t af[8][4];
    {
        int rA = wrow + g, rB = rA + 8;
        #pragma unroll
        for (int kt = 0; kt < 8; kt++) {
            af[kt][0] = zs32[rA * 68 + kt * 8 + t];
            af[kt][1] = zs32[rB * 68 + kt * 8 + t];
            af[kt][2] = zs32[rA * 68 + kt * 8 + 4 + t];
            af[kt][3] = zs32[rB * 68 + kt * 8 + 4 + t];
        }
    }

    float tminA = 3.4e38f, tminB = 3.4e38f;
    const int rA = wrow + g, rB = rA + 8;

    for (int c = 0; c < 8; c++) {
        __syncthreads();
        // Stage codebook chunk [c*128, c*128+128) bf16 -> cbs[code][136 halves]
        {
            const uint4* src = (const uint4*)(g_cbh + (size_t)c * 128 * CC);
            for (int i = tid; i < 128 * 16; i += 256) {
                int code = i >> 4, seg = i & 15;
                *(uint4*)(smem + CBS_OFF + code * 272 + seg * 16) =
                    src[code * 16 + seg];
            }
        }
        __syncthreads();

        for (int j = 0; j < 16; j++) {
            float d0 = 0.f, d1 = 0.f, d2 = 0.f, d3 = 0.f;
            const int brow = (j * 8 + g) * 68;
            #pragma unroll
            for (int kt = 0; kt < 8; kt++) {
                uint32_t b0 = cbs32[brow + kt * 8 + t];
                uint32_t b1 = cbs32[brow + kt * 8 + 4 + t];
                asm volatile(
                    "mma.sync.aligned.m16n8k16.row.col.f32.bf16.bf16.f32 "
                    "{%0,%1,%2,%3}, {%4,%5,%6,%7}, {%8,%9}, {%0,%1,%2,%3};"
                    : "+f"(d0), "+f"(d1), "+f"(d2), "+f"(d3)
                    : "r"(af[kt][0]), "r"(af[kt][1]), "r"(af[kt][2]), "r"(af[kt][3]),
                      "r"(b0), "r"(b1));
            }
            // scores: d0,d1 -> row rA cols (2t, 2t+1); d2,d3 -> row rB
            int code0 = c * 128 + j * 8 + 2 * t;
            float cc0 = ccs[code0], cc1 = ccs[code0 + 1];
            float s0 = fmaf(-2.f, d0, cc0);
            float s1 = fmaf(-2.f, d1, cc1);
            float s2 = fmaf(-2.f, d2, cc0);
            float s3 = fmaf(-2.f, d3, cc1);
            // exact per-row tile min (4 lanes share a row: reduce over t bits)
            float mA = fminf(s0, s1), mB = fminf(s2, s3);
            mA = fminf(mA, __shfl_xor_sync(0xffffffffu, mA, 1));
            mA = fminf(mA, __shfl_xor_sync(0xffffffffu, mA, 2));
            mB = fminf(mB, __shfl_xor_sync(0xffffffffu, mB, 1));
            mB = fminf(mB, __shfl_xor_sync(0xffffffffu, mB, 2));
            tminA = fminf(tminA, mA);
            tminB = fminf(tminB, mB);
            float thA = tminA + MARGIN, thB = tminB + MARGIN;
            if (s0 < thA) { int p = atomicAdd(&cnt[rA], 1); if (p < CAP) cand[rA*CAP+p] = (uint16_t)code0; }
            if (s1 < thA) { int p = atomicAdd(&cnt[rA], 1); if (p < CAP) cand[rA*CAP+p] = (uint16_t)(code0+1); }
            if (s2 < thB) { int p = atomicAdd(&cnt[rB], 1); if (p < CAP) cand[rB*CAP+p] = (uint16_t)code0; }
            if (s3 < thB) { int p = atomicAdd(&cnt[rB], 1); if (p < CAP) cand[rB*CAP+p] = (uint16_t)(code0+1); }
        }
    }
    __syncthreads();

    // ---- Exact rescoring phase ----
    // Re-stage exact fp32 z over the zs/cbs region: zex[hw][129] (66048 B).
    float* zex = (float*)smem;
    for (int i = tid; i < 128 * 128; i += 256) {
        int k = i >> 7, hw = i & 127;
        zex[hw * 129 + k] = zb[k * HW + hw];
    }
    __syncthreads();

    if (tid < 128) {
        const float* zr = zex + tid * 129;
        // S_z: strictly sequential fp32 chain (matches ref jnp.sum(z*z))
        float sz = 0.f;
        for (int k = 0; k < CC; k++)
            sz = __fadd_rn(sz, __fmul_rn(zr[k], zr[k]));

        int nc = cnt[tid];
        float best = 3.4e38f;
        int   bidx = 0x7fffffff;
        if (nc <= CAP) {
            for (int i = 0; i < nc; i++) {
                int code = cand[tid * CAP + i];
                const float* cr = cb + code * CC;
                float gacc = 0.f;
                #pragma unroll 8
                for (int k = 0; k < CC; k++) gacc = fmaf(zr[k], cr[k], gacc);
                float d2 = __fadd_rn(__fsub_rn(sz, __fmul_rn(2.f, gacc)), ccs[code]);
                if (d2 < best || (d2 == best && code < bidx)) { best = d2; bidx = code; }
            }
        } else {
            // overflow fallback (rare): exact scan of all codes, ascending
            for (int code = 0; code < KK; code++) {
                const float* cr = cb + code * CC;
                float gacc = 0.f;
                #pragma unroll 8
                for (int k = 0; k < CC; k++) gacc = fmaf(zr[k], cr[k], gacc);
                float d2 = __fadd_rn(__fsub_rn(sz, __fmul_rn(2.f, gacc)), ccs[code]);
                if (d2 < best) { best = d2; bidx = code; }
            }
        }
        g_idx[n0 + tid] = bidx;
        out_idx_f[n0 + tid] = (float)bidx;
    }
}

// ---------------------------------------------------------------------------
// K3: gather codebook rows, write quantized, loss partials, counts.
// ---------------------------------------------------------------------------
__global__ __launch_bounds__(256)
void k_quant(const float* __restrict__ z, const float* __restrict__ cb,
             float* __restrict__ out_q) {
    __shared__ int   idx_s[64];
    __shared__ float qs[64][129];
    __shared__ double red[256];

    const int tid = threadIdx.x;
    const int n0  = blockIdx.x * 64;
    const int b   = n0 >> 12;
    const int hw0 = n0 & 4095;

    if (tid < 64) {
        int idx = g_idx[n0 + tid];
        idx_s[tid] = idx;
        atomicAdd(&g_counts[idx], 1);
    }
    __syncthreads();

    for (int g = tid; g < 64 * 128; g += 256) {
        int hw = g >> 7, k = g & 127;
        qs[hw][k] = cb[idx_s[hw] * CC + k];
    }
    __syncthreads();

    const float* zb = z     + (size_t)b * CC * HW + hw0;
    float*       ob = out_q + (size_t)b * CC * HW + hw0;
    const int hw = tid & 63;
    const int c0 = tid >> 6;

    double acc = 0.0;
    #pragma unroll 8
    for (int i = 0; i < 32; i++) {
        int c = c0 + i * 4;
        float zv = zb[c * HW + hw];
        float qv = qs[hw][c];
        ob[c * HW + hw] = __fadd_rn(zv, __fsub_rn(qv, zv));
        float d = __fsub_rn(zv, qv);
        acc += (double)d * (double)d;
    }

    red[tid] = acc;
    __syncthreads();
    #pragma unroll
    for (int s = 128; s > 0; s >>= 1) {
        if (tid < s) red[tid] += red[tid + s];
        __syncthreads();
    }
    if (tid == 0) g_partial[blockIdx.x] = red[0];
}

// ---------------------------------------------------------------------------
// K4: finalize — vq_loss and perplexity
// ---------------------------------------------------------------------------
__global__ __launch_bounds__(256)
void k_final(float* __restrict__ out) {
    __shared__ double red[256];
    const int tid = threadIdx.x;

    double a = 0.0;
    for (int i = tid; i < NN/64; i += 256) a += g_partial[i];
    red[tid] = a;
    __syncthreads();
    #pragma unroll
    for (int s = 128; s > 0; s >>= 1) {
        if (tid < s) red[tid] += red[tid + s];
        __syncthreads();
    }
    if (tid == 0) {
        double mse = red[0] / (double)Q_ELEMS;
        float m = (float)mse;
        out[OUT_SCAL_OFF + 0] = __fadd_rn(m, 0.25f * m);
    }
    __syncthreads();

    double e = 0.0;
    for (int i = tid; i < KK; i += 256) {
        float p = (float)g_counts[i] / 65536.0f;
        float term = p * logf(p + 1e-10f);
        e += (double)term;
    }
    red[tid] = e;
    __syncthreads();
    #pragma unroll
    for (int s = 128; s > 0; s >>= 1) {
        if (tid < s) red[tid] += red[tid + s];
        __syncthreads();
    }
    if (tid == 0)
        out[OUT_SCAL_OFF + 1] = expf((float)(-red[0]));
}

// ---------------------------------------------------------------------------
extern "C" void kernel_launch(void* const* d_in, const int* in_sizes, int n_in,
                              void* d_out, int out_size) {
    const float* z  = (const float*)d_in[0];  // [16,128,64,64]
    const float* cb = (const float*)d_in[1];  // [1024,128]
    float* out = (float*)d_out;               // [quantized | indices | vq | ppl]

    static bool attr_set = false;
    if (!attr_set) {
        cudaFuncSetAttribute(k_screen, cudaFuncAttributeMaxDynamicSharedMemorySize,
                             SM_DYN);
        attr_set = true;
    }

    k_prep  <<<512, 256>>>(cb);
    k_screen<<<NN / M_CTA, 256, SM_DYN>>>(z, cb, out + OUT_IDX_OFF);
    k_quant <<<NN / 64, 256>>>(z, cb, out);
    k_final <<<1, 256>>>(out);
}